// round 14
// baseline (speedup 1.0000x reference)
#include <cuda_runtime.h>
#include <cuda_fp16.h>
#include <mma.h>

using namespace nvcuda;

#define B_  16
#define NK_ 256
#define NQ_ 256
#define DK_ 256
#define H_  128
#define DV_ 256
#define KT  4     // k-rows per attn tile
#define PRT 16    // rows per proj block (one m16 tile)

// scratch (allocation-free rule: device globals)
__device__ float  g_kproj[B_ * NK_ * H_];   // (B, NK, H)
__device__ float  g_qproj[B_ * NQ_ * H_];   // (B, NQ, H)
__device__ __half g_WHi[2 * DK_ * H_];      // [0]=Wk, [1]=Wq, hi fp16
__device__ __half g_WLo[2 * DK_ * H_];      // residual lo fp16

__device__ __forceinline__ float tanh_fast(float x) {
    float y;
    asm("tanh.approx.f32 %0, %1;" : "=f"(y) : "f"(x));
    return y;
}

// ---------------------------------------------------------------------------
// Kernel 0: split Wk/Wq into fp16 hi + lo residual (W = hi + lo to ~2^-21).
// ---------------------------------------------------------------------------
__global__ __launch_bounds__(256)
void prep_w(const float* __restrict__ Wk, const float* __restrict__ Wq) {
    int i = blockIdx.x * 256 + threadIdx.x;          // 0 .. 65535
    const float* W = (i < DK_ * H_) ? Wk : Wq;
    int j = i & (DK_ * H_ - 1);
    float w = W[j];
    __half hi = __float2half_rn(w);
    g_WHi[i] = hi;
    g_WLo[i] = __float2half_rn(w - __half2float(hi));
}

// ---------------------------------------------------------------------------
// Kernel A: tensor-core projections. Block = 128 threads (4 warps), PRT=16
// rows, all 128 output cols. Warp w owns cols [w*32, w*32+32) as 2 m16n16
// fragments. W applied as hi+lo (2 MMAs) -> W quantization error ~0.
// A (input rows) converted fp32->fp16 while staging (single quantization).
// qproj tiles fully masked by valid_lens exit early.
// ---------------------------------------------------------------------------
__global__ __launch_bounds__(128)
void proj_kernel(const float* __restrict__ key,
                 const float* __restrict__ query,
                 const int*   __restrict__ valid_lens) {
    const int r0  = blockIdx.x * PRT;
    const int isQ = blockIdx.y;

    if (isQ) {
        const int vl = valid_lens[r0 >> 8];
        if ((r0 & (NQ_ - 1)) >= vl) return;   // whole q-row-range masked
    }

    __shared__ __align__(16) __half Asm[PRT * DK_];   // 16x256 fp16 = 8KB
    __shared__ __align__(16) __half Bhi[16 * H_];     // 16x128 fp16 = 4KB
    __shared__ __align__(16) __half Blo[16 * H_];     // 4KB

    const float*  in  = isQ ? query : key;
    const __half* WHi = g_WHi + isQ * (DK_ * H_);
    const __half* WLo = g_WLo + isQ * (DK_ * H_);
    float* out = (isQ ? g_qproj : g_kproj) + (size_t)r0 * H_;

    const int t   = threadIdx.x;          // 0..127
    const int wid = t >> 5;
    const int col0 = wid * 32;

    // stage A: 16 rows x 256, fp32 -> fp16. thread: row t>>3, 32 elems.
    {
        const int r  = t >> 3;
        const int c0 = (t & 7) * 32;
        const float* src = in + (size_t)(r0 + r) * DK_ + c0;
        __half* dst = &Asm[r * DK_ + c0];
        #pragma unroll
        for (int i = 0; i < 8; ++i) {
            float4 v = *reinterpret_cast<const float4*>(src + i * 4);
            *reinterpret_cast<__half2*>(dst + i * 4)     = __floats2half2_rn(v.x, v.y);
            *reinterpret_cast<__half2*>(dst + i * 4 + 2) = __floats2half2_rn(v.z, v.w);
        }
    }

    wmma::fragment<wmma::accumulator, 16, 16, 16, float> acc0, acc1;
    wmma::fill_fragment(acc0, 0.0f);
    wmma::fill_fragment(acc1, 0.0f);

    for (int ks = 0; ks < DK_ / 16; ++ks) {
        __syncthreads();   // previous-iter B consumed (and 1st iter: A staged)
        // stage W tile rows [ks*16, ks*16+16) x 128: contiguous 2048 halves
        {
            const int off = t * 16;                    // 16 halves per thread
            const __half* sH = WHi + ks * 16 * H_;
            const __half* sL = WLo + ks * 16 * H_;
            *reinterpret_cast<int4*>(&Bhi[off])     = *reinterpret_cast<const int4*>(&sH[off]);
            *reinterpret_cast<int4*>(&Bhi[off + 8]) = *reinterpret_cast<const int4*>(&sH[off + 8]);
            *reinterpret_cast<int4*>(&Blo[off])     = *reinterpret_cast<const int4*>(&sL[off]);
            *reinterpret_cast<int4*>(&Blo[off + 8]) = *reinterpret_cast<const int4*>(&sL[off + 8]);
        }
        __syncthreads();

        wmma::fragment<wmma::matrix_a, 16, 16, 16, __half, wmma::row_major> a;
        wmma::load_matrix_sync(a, &Asm[ks * 16], DK_);

        wmma::fragment<wmma::matrix_b, 16, 16, 16, __half, wmma::row_major> b;
        wmma::load_matrix_sync(b, &Bhi[col0], H_);
        wmma::mma_sync(acc0, a, b, acc0);
        wmma::load_matrix_sync(b, &Blo[col0], H_);
        wmma::mma_sync(acc0, a, b, acc0);
        wmma::load_matrix_sync(b, &Bhi[col0 + 16], H_);
        wmma::mma_sync(acc1, a, b, acc1);
        wmma::load_matrix_sync(b, &Blo[col0 + 16], H_);
        wmma::mma_sync(acc1, a, b, acc1);
    }

    wmma::store_matrix_sync(&out[col0],      acc0, H_, wmma::mem_row_major);
    wmma::store_matrix_sync(&out[col0 + 16], acc1, H_, wmma::mem_row_major);
}

// ---------------------------------------------------------------------------
// Kernel B: EXACT R9 champion (KT=4, 256 threads, fp32 tanh, no-max softmax,
// valid_lens early-skip, row-major qproj loads).
// ---------------------------------------------------------------------------
__global__ __launch_bounds__(256)
void attn_kernel(const float* __restrict__ value,
                 const int*   __restrict__ valid_lens,
                 const float* __restrict__ wv,
                 float*       __restrict__ out) {
    const int bk0 = blockIdx.x * KT;
    const int b   = bk0 >> 8;            // NK = 256
    const int t   = threadIdx.x;         // 0..255
    const int lane = t & 31;
    const int wid  = t >> 5;

    __shared__ __align__(16) float kvs[KT * H_];       // 2KB
    __shared__ __align__(16) float wvs[H_];
    __shared__ __align__(16) float attnT[NQ_ * KT];    // 4KB, attnT[q*KT + k]
    __shared__ float redm[KT][8];
    __shared__ float gred[KT];

    const int vl = valid_lens[b];

    // stage KT kproj rows + wv
    {
        const float* src = g_kproj + (size_t)bk0 * H_;   // 512 floats
        *reinterpret_cast<float2*>(&kvs[t * 2]) =
            *reinterpret_cast<const float2*>(src + t * 2);
        if (t < H_) wvs[t] = wv[t];
    }
    __syncthreads();

    // ---- Phase 1: scores + exp for q = t, all KT k (skip masked q) ----
    float e[KT];
    if (t < vl) {
        const float* qrow = g_qproj + (size_t)(b * NQ_ + t) * H_;
        float s[KT];
        #pragma unroll
        for (int k = 0; k < KT; ++k) s[k] = 0.f;

        #pragma unroll 2
        for (int h = 0; h < H_; h += 4) {
            float4 qv  = *reinterpret_cast<const float4*>(qrow + h);
            float4 wv4 = *reinterpret_cast<const float4*>(&wvs[h]);
            #pragma unroll
            for (int k = 0; k < KT; ++k) {
                float4 kv = *reinterpret_cast<const float4*>(&kvs[k * H_ + h]);
                s[k] = fmaf(wv4.x, tanh_fast(kv.x + qv.x), s[k]);
                s[k] = fmaf(wv4.y, tanh_fast(kv.y + qv.y), s[k]);
                s[k] = fmaf(wv4.z, tanh_fast(kv.z + qv.z), s[k]);
                s[k] = fmaf(wv4.w, tanh_fast(kv.w + qv.w), s[k]);
            }
        }
        #pragma unroll
        for (int k = 0; k < KT; ++k)
            e[k] = __expf(s[k]);          // |s| <= ~9, safe without max-sub
    } else {
        #pragma unroll
        for (int k = 0; k < KT; ++k) e[k] = 0.f;
    }

    // ---- Phase 2: sum-only softmax reduction per k over 256 q ----
    #pragma unroll
    for (int k = 0; k < KT; ++k) {
        float sm = e[k];
        #pragma unroll
        for (int o = 16; o > 0; o >>= 1)
            sm += __shfl_xor_sync(0xffffffffu, sm, o);
        if (lane == 0) redm[k][wid] = sm;
    }
    __syncthreads();
    if (t < 32) {                        // one warp: k = t>>3 (0..3)
        int k = t >> 3, w = t & 7;
        float v = redm[k][w];
        v += __shfl_xor_sync(0xffffffffu, v, 4);
        v += __shfl_xor_sync(0xffffffffu, v, 2);
        v += __shfl_xor_sync(0xffffffffu, v, 1);
        if (w == 0) gred[k] = v;
    }
    __syncthreads();

    {
        float4 a;
        a.x = e[0] * __frcp_rn(gred[0]);
        a.y = e[1] * __frcp_rn(gred[1]);
        a.z = e[2] * __frcp_rn(gred[2]);
        a.w = e[3] * __frcp_rn(gred[3]);
        *reinterpret_cast<float4*>(&attnT[t * KT]) = a;
    }
    __syncthreads();

    // ---- Phase 3: out[b, bk0+k, d], d = t; only q < vl contribute ----
    const float* vcol = value + (size_t)b * NQ_ * DV_ + t;
    float a0 = 0.f, a1 = 0.f, a2 = 0.f, a3 = 0.f;

    int q = 0;
    const int vl4 = vl & ~3;
    for (; q < vl4; q += 4) {
        #pragma unroll
        for (int j = 0; j < 4; ++j) {
            float v = vcol[(size_t)(q + j) * DV_];
            float4 a = *reinterpret_cast<const float4*>(&attnT[(q + j) * KT]);
            a0 = fmaf(a.x, v, a0);
            a1 = fmaf(a.y, v, a1);
            a2 = fmaf(a.z, v, a2);
            a3 = fmaf(a.w, v, a3);
        }
    }
    for (; q < vl; ++q) {
        float v = vcol[(size_t)q * DV_];
        float4 a = *reinterpret_cast<const float4*>(&attnT[q * KT]);
        a0 = fmaf(a.x, v, a0);
        a1 = fmaf(a.y, v, a1);
        a2 = fmaf(a.z, v, a2);
        a3 = fmaf(a.w, v, a3);
    }

    out[(size_t)(bk0 + 0) * DV_ + t] = a0;
    out[(size_t)(bk0 + 1) * DV_ + t] = a1;
    out[(size_t)(bk0 + 2) * DV_ + t] = a2;
    out[(size_t)(bk0 + 3) * DV_ + t] = a3;
}

// ---------------------------------------------------------------------------
extern "C" void kernel_launch(void* const* d_in, const int* in_sizes, int n_in,
                              void* d_out, int out_size) {
    const float* key        = (const float*)d_in[0];
    const float* query      = (const float*)d_in[1];
    const float* value      = (const float*)d_in[2];
    const int*   valid_lens = (const int*)  d_in[3];
    const float* Wk         = (const float*)d_in[4];
    const float* Wq         = (const float*)d_in[5];
    const float* wv         = (const float*)d_in[6];
    float* out = (float*)d_out;

    prep_w<<<2 * DK_ * H_ / 256, 256>>>(Wk, Wq);
    dim3 gridA(B_ * NK_ / PRT, 2);
    proj_kernel<<<gridA, 128>>>(key, query, valid_lens);
    attn_kernel<<<B_ * NK_ / KT, 256>>>(value, valid_lens, wv, out);
}

// round 15
// speedup vs baseline: 1.1235x; 1.1235x over previous
#include <cuda_runtime.h>
#include <cuda_fp16.h>
#include <mma.h>

using namespace nvcuda;

#define B_  16
#define NK_ 256
#define NQ_ 256
#define DK_ 256
#define H_  128
#define DV_ 256
#define KT  4     // k-rows per attn tile
#define PRT 16    // rows per proj block (one m16 tile)

// scratch (allocation-free rule: device globals)
__device__ float  g_kproj[B_ * NK_ * H_];   // (B, NK, H)
__device__ float  g_qproj[B_ * NQ_ * H_];   // (B, NQ, H)
__device__ __half g_WHi[2 * DK_ * H_];      // [0]=Wk, [1]=Wq, hi fp16
__device__ __half g_WLo[2 * DK_ * H_];      // residual lo fp16

__device__ __forceinline__ float tanh_fast(float x) {
    float y;
    asm("tanh.approx.f32 %0, %1;" : "=f"(y) : "f"(x));
    return y;
}

// ---------------------------------------------------------------------------
// Kernel 0: split Wk/Wq into fp16 hi + lo residual (W = hi + lo to ~2^-21).
// ---------------------------------------------------------------------------
__global__ __launch_bounds__(256)
void prep_w(const float* __restrict__ Wk, const float* __restrict__ Wq) {
    int i = blockIdx.x * 256 + threadIdx.x;          // 0 .. 65535
    const float* W = (i < DK_ * H_) ? Wk : Wq;
    int j = i & (DK_ * H_ - 1);
    float w = W[j];
    __half hi = __float2half_rn(w);
    g_WHi[i] = hi;
    g_WLo[i] = __float2half_rn(w - __half2float(hi));
}

// ---------------------------------------------------------------------------
// Kernel A: tensor-core projections, B fragments loaded DIRECTLY FROM GLOBAL
// (L1-resident: WHi+WLo = 128KB fp16, reused by all co-resident blocks).
// Block = 128 threads (4 warps), PRT=16 rows x 128 cols; warp w owns cols
// [w*32, w*32+32) as 2 fp32-accum fragments. A staged once in smem (fp16),
// ONE barrier per block, no B staging, no per-step barriers.
// qproj tiles fully masked by valid_lens exit early.
// ---------------------------------------------------------------------------
__global__ __launch_bounds__(128)
void proj_kernel(const float* __restrict__ key,
                 const float* __restrict__ query,
                 const int*   __restrict__ valid_lens) {
    const int r0  = blockIdx.x * PRT;
    const int isQ = blockIdx.y;

    if (isQ) {
        const int vl = valid_lens[r0 >> 8];
        if ((r0 & (NQ_ - 1)) >= vl) return;   // whole q-row-range masked
    }

    __shared__ __align__(16) __half Asm[PRT * DK_];   // 16x256 fp16 = 8KB

    const float*  in  = isQ ? query : key;
    const __half* WHi = g_WHi + isQ * (DK_ * H_);
    const __half* WLo = g_WLo + isQ * (DK_ * H_);
    float* out = (isQ ? g_qproj : g_kproj) + (size_t)r0 * H_;

    const int t    = threadIdx.x;         // 0..127
    const int wid  = t >> 5;
    const int col0 = wid * 32;

    // stage A: 16 rows x 256, fp32 -> fp16. thread: row t>>3, 32 elems.
    {
        const int r  = t >> 3;
        const int c0 = (t & 7) * 32;
        const float* src = in + (size_t)(r0 + r) * DK_ + c0;
        __half* dst = &Asm[r * DK_ + c0];
        #pragma unroll
        for (int i = 0; i < 8; ++i) {
            float4 v = *reinterpret_cast<const float4*>(src + i * 4);
            *reinterpret_cast<__half2*>(dst + i * 4)     = __floats2half2_rn(v.x, v.y);
            *reinterpret_cast<__half2*>(dst + i * 4 + 2) = __floats2half2_rn(v.z, v.w);
        }
    }
    __syncthreads();

    wmma::fragment<wmma::accumulator, 16, 16, 16, float> acc0, acc1;
    wmma::fill_fragment(acc0, 0.0f);
    wmma::fill_fragment(acc1, 0.0f);

    #pragma unroll 4
    for (int ks = 0; ks < DK_ / 16; ++ks) {
        wmma::fragment<wmma::matrix_a, 16, 16, 16, __half, wmma::row_major> a;
        wmma::load_matrix_sync(a, &Asm[ks * 16], DK_);

        const __half* bHi = WHi + ks * 16 * H_;
        const __half* bLo = WLo + ks * 16 * H_;

        wmma::fragment<wmma::matrix_b, 16, 16, 16, __half, wmma::row_major> b;
        wmma::load_matrix_sync(b, bHi + col0, H_);         // global, L1-hit
        wmma::mma_sync(acc0, a, b, acc0);
        wmma::load_matrix_sync(b, bLo + col0, H_);
        wmma::mma_sync(acc0, a, b, acc0);
        wmma::load_matrix_sync(b, bHi + col0 + 16, H_);
        wmma::mma_sync(acc1, a, b, acc1);
        wmma::load_matrix_sync(b, bLo + col0 + 16, H_);
        wmma::mma_sync(acc1, a, b, acc1);
    }

    wmma::store_matrix_sync(&out[col0],      acc0, H_, wmma::mem_row_major);
    wmma::store_matrix_sync(&out[col0 + 16], acc1, H_, wmma::mem_row_major);
}

// ---------------------------------------------------------------------------
// Kernel B: EXACT R9 champion (KT=4, 256 threads, fp32 tanh, no-max softmax,
// valid_lens early-skip, row-major qproj loads).
// ---------------------------------------------------------------------------
__global__ __launch_bounds__(256)
void attn_kernel(const float* __restrict__ value,
                 const int*   __restrict__ valid_lens,
                 const float* __restrict__ wv,
                 float*       __restrict__ out) {
    const int bk0 = blockIdx.x * KT;
    const int b   = bk0 >> 8;            // NK = 256
    const int t   = threadIdx.x;         // 0..255
    const int lane = t & 31;
    const int wid  = t >> 5;

    __shared__ __align__(16) float kvs[KT * H_];       // 2KB
    __shared__ __align__(16) float wvs[H_];
    __shared__ __align__(16) float attnT[NQ_ * KT];    // 4KB, attnT[q*KT + k]
    __shared__ float redm[KT][8];
    __shared__ float gred[KT];

    const int vl = valid_lens[b];

    // stage KT kproj rows + wv
    {
        const float* src = g_kproj + (size_t)bk0 * H_;   // 512 floats
        *reinterpret_cast<float2*>(&kvs[t * 2]) =
            *reinterpret_cast<const float2*>(src + t * 2);
        if (t < H_) wvs[t] = wv[t];
    }
    __syncthreads();

    // ---- Phase 1: scores + exp for q = t, all KT k (skip masked q) ----
    float e[KT];
    if (t < vl) {
        const float* qrow = g_qproj + (size_t)(b * NQ_ + t) * H_;
        float s[KT];
        #pragma unroll
        for (int k = 0; k < KT; ++k) s[k] = 0.f;

        #pragma unroll 2
        for (int h = 0; h < H_; h += 4) {
            float4 qv  = *reinterpret_cast<const float4*>(qrow + h);
            float4 wv4 = *reinterpret_cast<const float4*>(&wvs[h]);
            #pragma unroll
            for (int k = 0; k < KT; ++k) {
                float4 kv = *reinterpret_cast<const float4*>(&kvs[k * H_ + h]);
                s[k] = fmaf(wv4.x, tanh_fast(kv.x + qv.x), s[k]);
                s[k] = fmaf(wv4.y, tanh_fast(kv.y + qv.y), s[k]);
                s[k] = fmaf(wv4.z, tanh_fast(kv.z + qv.z), s[k]);
                s[k] = fmaf(wv4.w, tanh_fast(kv.w + qv.w), s[k]);
            }
        }
        #pragma unroll
        for (int k = 0; k < KT; ++k)
            e[k] = __expf(s[k]);          // |s| <= ~9, safe without max-sub
    } else {
        #pragma unroll
        for (int k = 0; k < KT; ++k) e[k] = 0.f;
    }

    // ---- Phase 2: sum-only softmax reduction per k over 256 q ----
    #pragma unroll
    for (int k = 0; k < KT; ++k) {
        float sm = e[k];
        #pragma unroll
        for (int o = 16; o > 0; o >>= 1)
            sm += __shfl_xor_sync(0xffffffffu, sm, o);
        if (lane == 0) redm[k][wid] = sm;
    }
    __syncthreads();
    if (t < 32) {                        // one warp: k = t>>3 (0..3)
        int k = t >> 3, w = t & 7;
        float v = redm[k][w];
        v += __shfl_xor_sync(0xffffffffu, v, 4);
        v += __shfl_xor_sync(0xffffffffu, v, 2);
        v += __shfl_xor_sync(0xffffffffu, v, 1);
        if (w == 0) gred[k] = v;
    }
    __syncthreads();

    {
        float4 a;
        a.x = e[0] * __frcp_rn(gred[0]);
        a.y = e[1] * __frcp_rn(gred[1]);
        a.z = e[2] * __frcp_rn(gred[2]);
        a.w = e[3] * __frcp_rn(gred[3]);
        *reinterpret_cast<float4*>(&attnT[t * KT]) = a;
    }
    __syncthreads();

    // ---- Phase 3: out[b, bk0+k, d], d = t; only q < vl contribute ----
    const float* vcol = value + (size_t)b * NQ_ * DV_ + t;
    float a0 = 0.f, a1 = 0.f, a2 = 0.f, a3 = 0.f;

    int q = 0;
    const int vl4 = vl & ~3;
    for (; q < vl4; q += 4) {
        #pragma unroll
        for (int j = 0; j < 4; ++j) {
            float v = vcol[(size_t)(q + j) * DV_];
            float4 a = *reinterpret_cast<const float4*>(&attnT[(q + j) * KT]);
            a0 = fmaf(a.x, v, a0);
            a1 = fmaf(a.y, v, a1);
            a2 = fmaf(a.z, v, a2);
            a3 = fmaf(a.w, v, a3);
        }
    }
    for (; q < vl; ++q) {
        float v = vcol[(size_t)q * DV_];
        float4 a = *reinterpret_cast<const float4*>(&attnT[q * KT]);
        a0 = fmaf(a.x, v, a0);
        a1 = fmaf(a.y, v, a1);
        a2 = fmaf(a.z, v, a2);
        a3 = fmaf(a.w, v, a3);
    }

    out[(size_t)(bk0 + 0) * DV_ + t] = a0;
    out[(size_t)(bk0 + 1) * DV_ + t] = a1;
    out[(size_t)(bk0 + 2) * DV_ + t] = a2;
    out[(size_t)(bk0 + 3) * DV_ + t] = a3;
}

// ---------------------------------------------------------------------------
extern "C" void kernel_launch(void* const* d_in, const int* in_sizes, int n_in,
                              void* d_out, int out_size) {
    const float* key        = (const float*)d_in[0];
    const float* query      = (const float*)d_in[1];
    const float* value      = (const float*)d_in[2];
    const int*   valid_lens = (const int*)  d_in[3];
    const float* Wk         = (const float*)d_in[4];
    const float* Wq         = (const float*)d_in[5];
    const float* wv         = (const float*)d_in[6];
    float* out = (float*)d_out;

    prep_w<<<2 * DK_ * H_ / 256, 256>>>(Wk, Wq);
    dim3 gridA(B_ * NK_ / PRT, 2);
    proj_kernel<<<gridA, 128>>>(key, query, valid_lens);
    attn_kernel<<<B_ * NK_ / KT, 256>>>(value, valid_lens, wv, out);
}